// round 8
// baseline (speedup 1.0000x reference)
#include <cuda_runtime.h>
#include <cuda_fp16.h>
#include <cstdint>
#include <math.h>

// ---------------------------------------------------------------------------
// Problem constants
// ---------------------------------------------------------------------------
#define E_DIM   1024
#define HID_DIM 4096
#define WSZ     64
#define M_TOK   16384

// ---------------------------------------------------------------------------
// Scratch (__device__ globals; no allocation allowed)
// ---------------------------------------------------------------------------
__device__ float  g_AT [M_TOK * E_DIM];
__device__ float  g_X1 [M_TOK * E_DIM];
__device__ float  g_F  [M_TOK * E_DIM];
__device__ __half g_Qh [M_TOK * E_DIM];
__device__ __half g_Kh [M_TOK * E_DIM];
__device__ __half g_Vh [M_TOK * E_DIM];
__device__ __half g_xh [M_TOK * E_DIM];
__device__ __half g_X1h[M_TOK * E_DIM];
__device__ __half g_Hh [(size_t)M_TOK * HID_DIM];
__device__ __half g_Wqh[E_DIM * E_DIM];
__device__ __half g_Wkh[E_DIM * E_DIM];
__device__ __half g_Wvh[E_DIM * E_DIM];
__device__ __half g_W1h[(size_t)E_DIM * HID_DIM];
__device__ __half g_W2h[(size_t)E_DIM * HID_DIM];

// ---------------------------------------------------------------------------
// PTX helpers
// ---------------------------------------------------------------------------
__device__ __forceinline__ uint32_t smem_to_u32(const void* p) {
    uint32_t a;
    asm("{ .reg .u64 t; cvta.to.shared.u64 t, %1; cvt.u32.u64 %0, t; }"
        : "=r"(a) : "l"(p));
    return a;
}

#define CP_ASYNC16(saddr, gptr) \
    asm volatile("cp.async.cg.shared.global [%0], [%1], 16;" \
                 :: "r"(saddr), "l"(gptr))
#define CP_COMMIT() asm volatile("cp.async.commit_group;" ::: "memory")
#define CP_WAIT(n)  asm volatile("cp.async.wait_group %0;" :: "n"(n) : "memory")

#define LDMATRIX_X4(r0, r1, r2, r3, addr) \
    asm volatile("ldmatrix.sync.aligned.m8n8.x4.shared.b16 {%0,%1,%2,%3}, [%4];" \
                 : "=r"(r0), "=r"(r1), "=r"(r2), "=r"(r3) : "r"(addr))

#define LDMATRIX_X4_TRANS(r0, r1, r2, r3, addr) \
    asm volatile("ldmatrix.sync.aligned.m8n8.x4.trans.shared.b16 {%0,%1,%2,%3}, [%4];" \
                 : "=r"(r0), "=r"(r1), "=r"(r2), "=r"(r3) : "r"(addr))

__device__ __forceinline__ void mma_fp16(float* c, const uint32_t* a, const uint32_t* b) {
    asm volatile(
        "mma.sync.aligned.m16n8k16.row.col.f32.f16.f16.f32 "
        "{%0,%1,%2,%3}, {%4,%5,%6,%7}, {%8,%9}, {%0,%1,%2,%3};"
        : "+f"(c[0]), "+f"(c[1]), "+f"(c[2]), "+f"(c[3])
        : "r"(a[0]), "r"(a[1]), "r"(a[2]), "r"(a[3]), "r"(b[0]), "r"(b[1]));
}

// ---------------------------------------------------------------------------
// Elementwise f32 -> f16 conversion
// ---------------------------------------------------------------------------
__global__ __launch_bounds__(256)
void to_half_kernel(const float* __restrict__ in, __half* __restrict__ out, size_t n4)
{
    const size_t i = (size_t)blockIdx.x * 256 + threadIdx.x;
    if (i >= n4) return;
    const float4 v = ((const float4*)in)[i];
    __half2 h0 = __floats2half2_rn(v.x, v.y);
    __half2 h1 = __floats2half2_rn(v.z, v.w);
    uint2 pk;
    pk.x = *(uint32_t*)&h0;
    pk.y = *(uint32_t*)&h1;
    ((uint2*)out)[i] = pk;
}

// ---------------------------------------------------------------------------
// fp16 tensor-core GEMM: C[M,N] = A[M,K] @ B[K,N] + bias
// (optional ReLU; OUT_HALF stores fp16). A,B fp16; accum/bias fp32.
// 128x256x32 block tile, 256 threads (4x2 warps, 32x128 warp tile),
// 3-stage cp.async pipeline, ldmatrix fragment loads, 1 CTA/SM.
// blockIdx.z selects among up to 3 (B, bias, C) triples sharing A.
// ---------------------------------------------------------------------------
#define A_STRIDE_H 40     // halves per A row
#define B_STRIDE_H 264    // halves per B row (256 + 8 pad)
#define A_TILE_BYTES (128 * A_STRIDE_H * 2)   // 10240
#define B_TILE_BYTES (32 * B_STRIDE_H * 2)    // 16896
#define STAGE_BYTES  (A_TILE_BYTES + B_TILE_BYTES)   // 27136
#define GEMM_SMEM_BYTES (3 * STAGE_BYTES)            // 81408

struct GemmOuts {
    const __half* B[3];
    const float*  bias[3];
    void*         C[3];
};

template<int RELU, int OUT_HALF>
__global__ __launch_bounds__(256, 1)
void gemm_fp16(const __half* __restrict__ A, GemmOuts io,
               int M, int N, int K)
{
    extern __shared__ char smem[];
    const uint32_t sbase = smem_to_u32(smem);

    const int tid = threadIdx.x;
    const int wid = tid >> 5;
    const int lane = tid & 31;
    const int g = lane >> 2;    // 0..7
    const int t = lane & 3;     // 0..3

    const int wm = wid & 3;     // warp row (4) -> 32 rows each
    const int wn = wid >> 2;    // warp col (2) -> 128 cols each

    const int m0 = blockIdx.y * 128;
    const int n0 = blockIdx.x * 256;
    const int z  = blockIdx.z;

    const __half* Bmat = io.B[z];
    const float*  bias = io.bias[z];

    const __half* Ag = A + (size_t)m0 * K;
    const __half* Bg = Bmat + n0;

    // Load one 128x32 A tile + 32x256 B tile (fp16) into the given stage
    auto load_tile = [&](int k0, int stage) {
        const uint32_t aoff = sbase + (uint32_t)stage * STAGE_BYTES;
        const uint32_t boff = aoff + A_TILE_BYTES;
#pragma unroll
        for (int i = 0; i < 2; i++) {
            const int s = tid + i * 256;            // 0..511
            const int r = s >> 2, c8 = (s & 3) << 3;
            CP_ASYNC16(aoff + (uint32_t)(r * A_STRIDE_H + c8) * 2,
                       Ag + (size_t)r * K + k0 + c8);
        }
#pragma unroll
        for (int i = 0; i < 4; i++) {
            const int s = tid + i * 256;            // 0..1023
            const int r = s >> 5, c8 = (s & 31) << 3;
            CP_ASYNC16(boff + (uint32_t)(r * B_STRIDE_H + c8) * 2,
                       Bg + (size_t)(k0 + r) * N + c8);
        }
        CP_COMMIT();
    };

    float acc[2][16][4];
#pragma unroll
    for (int mi = 0; mi < 2; mi++)
#pragma unroll
        for (int ni = 0; ni < 16; ni++)
#pragma unroll
            for (int j = 0; j < 4; j++) acc[mi][ni][j] = 0.f;

    const int NK = K >> 5;
    load_tile(0, 0);
    load_tile(32, 1);

    // ldmatrix lane addressing
    const int a_row = wm * 32 + (lane & 7) + ((lane >> 3) & 1) * 8;  // + mi*16
    const int a_col = (lane >> 4) << 3;                              // + kk*16
    const int b_row = (lane & 7) + ((lane >> 3) & 1) * 8;            // + kk*16
    const int b_col = wn * 128 + ((lane >> 4) << 3);                 // + ni4*16

    for (int kt = 0; kt < NK; kt++) {
        if (kt + 2 < NK) load_tile((kt + 2) << 5, (kt + 2) % 3);
        else CP_COMMIT();           // keep group count uniform
        CP_WAIT(2);                 // chunk kt's group retired
        __syncthreads();

        const uint32_t sA = sbase + (uint32_t)(kt % 3) * STAGE_BYTES;
        const uint32_t sB = sA + A_TILE_BYTES;

#pragma unroll
        for (int kk = 0; kk < 2; kk++) {
            uint32_t a[2][4];
#pragma unroll
            for (int mi = 0; mi < 2; mi++) {
                const uint32_t addr = sA +
                    (uint32_t)((a_row + mi * 16) * A_STRIDE_H + a_col + kk * 16) * 2;
                LDMATRIX_X4(a[mi][0], a[mi][1], a[mi][2], a[mi][3], addr);
            }
#pragma unroll
            for (int ni4 = 0; ni4 < 8; ni4++) {
                uint32_t b[4];
                const uint32_t addr = sB +
                    (uint32_t)((b_row + kk * 16) * B_STRIDE_H + b_col + ni4 * 16) * 2;
                LDMATRIX_X4_TRANS(b[0], b[1], b[2], b[3], addr);
#pragma unroll
                for (int mi = 0; mi < 2; mi++) {
                    mma_fp16(acc[mi][2 * ni4],     a[mi], &b[0]);
                    mma_fp16(acc[mi][2 * ni4 + 1], a[mi], &b[2]);
                }
            }
        }
        __syncthreads();
    }

    // Epilogue: bias (+ReLU) and store (fp32 or fp16)
#pragma unroll
    for (int mi = 0; mi < 2; mi++) {
        const int row = m0 + wm * 32 + mi * 16 + g;
#pragma unroll
        for (int ni = 0; ni < 16; ni++) {
            const int col = n0 + wn * 128 + ni * 8 + t * 2;
            const float b0 = bias[col], b1 = bias[col + 1];
            float2 lo = make_float2(acc[mi][ni][0] + b0, acc[mi][ni][1] + b1);
            float2 hi = make_float2(acc[mi][ni][2] + b0, acc[mi][ni][3] + b1);
            if (RELU) {
                lo.x = fmaxf(lo.x, 0.f); lo.y = fmaxf(lo.y, 0.f);
                hi.x = fmaxf(hi.x, 0.f); hi.y = fmaxf(hi.y, 0.f);
            }
            if (OUT_HALF) {
                __half* Ch = (__half*)io.C[z];
                __half2 l2 = __floats2half2_rn(lo.x, lo.y);
                __half2 h2 = __floats2half2_rn(hi.x, hi.y);
                *(__half2*)(Ch + (size_t)row * N + col) = l2;
                *(__half2*)(Ch + (size_t)(row + 8) * N + col) = h2;
            } else {
                float* Cf = (float*)io.C[z];
                *(float2*)(Cf + (size_t)row * N + col) = lo;
                *(float2*)(Cf + (size_t)(row + 8) * N + col) = hi;
            }
        }
    }
}

// ---------------------------------------------------------------------------
// Tensor-core window attention: one block per 64-token window, 8 warps.
// ---------------------------------------------------------------------------
#define AT_S_STRIDE 68    // floats
#define AT_P_STRIDE 72    // halves
#define AT_QK_STRIDE 72   // halves
#define AT_V_STRIDE 136   // halves
#define AT_S_OFF 0
#define AT_P_OFF (64 * AT_S_STRIDE * 4)                 // 17408
#define AT_U_OFF (AT_P_OFF + 64 * AT_P_STRIDE * 2)      // 26624
#define AT_Q_BYTES (64 * AT_QK_STRIDE * 2)              // 9216
#define AT_QK_STAGE (2 * AT_Q_BYTES)                    // 18432
#define AT_V_STAGE (64 * AT_V_STRIDE * 2)               // 17408
#define AT_SMEM (AT_U_OFF + 2 * AT_QK_STAGE)            // 63488

__global__ __launch_bounds__(256, 2)
void window_attn_mma(const __half* __restrict__ Qh, const __half* __restrict__ Kh,
                     const __half* __restrict__ Vh, float* __restrict__ O)
{
    extern __shared__ char smem[];
    const uint32_t sbase = smem_to_u32(smem);
    float* Sf = (float*)smem;

    const int tid = threadIdx.x;
    const int wid = tid >> 5;
    const int lane = tid & 31;
    const int g = lane >> 2, t = lane & 3;
    const int wm = wid & 3;     // 4 m-warps x 16 rows
    const int wn = wid >> 2;    // 2 n-warps

    const int w = blockIdx.x;
    const __half* Qw = Qh + (size_t)w * WSZ * E_DIM;
    const __half* Kw = Kh + (size_t)w * WSZ * E_DIM;
    const __half* Vw = Vh + (size_t)w * WSZ * E_DIM;
    float* Ow = O + (size_t)w * WSZ * E_DIM;

    const int lrow  = (lane & 7) + ((lane >> 3) & 1) * 8;  // 0..15
    const int lcol8 = (lane >> 4) << 3;                    // 0 or 8

    // ---- Phase 1: S = Q K^T ----
    auto load_qk = [&](int kc, int st) {
        const uint32_t qoff = sbase + AT_U_OFF + (uint32_t)st * AT_QK_STAGE;
        const uint32_t koff = qoff + AT_Q_BYTES;
#pragma unroll
        for (int i = 0; i < 2; i++) {
            const int s = tid + i * 256;        // 0..511
            const int r = s >> 3, c8 = (s & 7) << 3;
            CP_ASYNC16(qoff + (uint32_t)(r * AT_QK_STRIDE + c8) * 2,
                       Qw + (size_t)r * E_DIM + kc * 64 + c8);
            CP_ASYNC16(koff + (uint32_t)(r * AT_QK_STRIDE + c8) * 2,
                       Kw + (size_t)r * E_DIM + kc * 64 + c8);
        }
        CP_COMMIT();
    };

    float accS[4][4];
#pragma unroll
    for (int nt = 0; nt < 4; nt++)
#pragma unroll
        for (int j = 0; j < 4; j++) accS[nt][j] = 0.f;

    load_qk(0, 0);
    for (int kc = 0; kc < 16; kc++) {
        if (kc < 15) { load_qk(kc + 1, (kc + 1) & 1); CP_WAIT(1); }
        else         { CP_WAIT(0); }
        __syncthreads();

        const uint32_t qs = sbase + AT_U_OFF + (uint32_t)(kc & 1) * AT_QK_STAGE;
        const uint32_t ks = qs + AT_Q_BYTES;

#pragma unroll
        for (int kt = 0; kt < 4; kt++) {
            uint32_t a[4];
            LDMATRIX_X4(a[0], a[1], a[2], a[3],
                qs + (uint32_t)((wm * 16 + lrow) * AT_QK_STRIDE + lcol8 + kt * 16) * 2);
            uint32_t b[2][4];
#pragma unroll
            for (int h = 0; h < 2; h++)
                LDMATRIX_X4(b[h][0], b[h][1], b[h][2], b[h][3],
                    ks + (uint32_t)((wn * 32 + h * 16 + lrow) * AT_QK_STRIDE + lcol8 + kt * 16) * 2);
#pragma unroll
            for (int nt = 0; nt < 4; nt++) {
                uint32_t bf[2] = { b[nt >> 1][nt & 1], b[nt >> 1][(nt & 1) + 2] };
                mma_fp16(accS[nt], a, bf);
            }
        }
        __syncthreads();
    }

    // scale & write S (fp32)
    const float SCALE = 0.03125f;  // 1024^-0.5
#pragma unroll
    for (int nt = 0; nt < 4; nt++) {
        const int row = wm * 16 + g;
        const int col = wn * 32 + nt * 8 + t * 2;
        Sf[row * AT_S_STRIDE + col]           = accS[nt][0] * SCALE;
        Sf[row * AT_S_STRIDE + col + 1]       = accS[nt][1] * SCALE;
        Sf[(row + 8) * AT_S_STRIDE + col]     = accS[nt][2] * SCALE;
        Sf[(row + 8) * AT_S_STRIDE + col + 1] = accS[nt][3] * SCALE;
    }
    __syncthreads();

    // ---- softmax (4 threads per row) -> P fp16 ----
    {
        const int row = tid >> 2;
        const int part = (tid & 3) << 4;
        float vb[16];
        float m = -1e30f;
#pragma unroll
        for (int j = 0; j < 16; j++) {
            vb[j] = Sf[row * AT_S_STRIDE + part + j];
            m = fmaxf(m, vb[j]);
        }
        m = fmaxf(m, __shfl_xor_sync(0xffffffffu, m, 1));
        m = fmaxf(m, __shfl_xor_sync(0xffffffffu, m, 2));
        float s = 0.f;
#pragma unroll
        for (int j = 0; j < 16; j++) { vb[j] = __expf(vb[j] - m); s += vb[j]; }
        s += __shfl_xor_sync(0xffffffffu, s, 1);
        s += __shfl_xor_sync(0xffffffffu, s, 2);
        const float inv = 1.f / s;
        __half* Ph = (__half*)(smem + AT_P_OFF);
#pragma unroll
        for (int j = 0; j < 16; j++)
            Ph[row * AT_P_STRIDE + part + j] = __float2half(vb[j] * inv);
    }
    __syncthreads();

    // ---- Phase 2: O = P V ----
    uint32_t pf[4][4];
#pragma unroll
    for (int kt = 0; kt < 4; kt++)
        LDMATRIX_X4(pf[kt][0], pf[kt][1], pf[kt][2], pf[kt][3],
            sbase + AT_P_OFF +
            (uint32_t)((wm * 16 + lrow) * AT_P_STRIDE + lcol8 + kt * 16) * 2);

    auto load_v = [&](int ec, int st) {
        const uint32_t voff = sbase + AT_U_OFF + (uint32_t)st * AT_V_STAGE;
#pragma unroll
        for (int i = 0; i < 4; i++) {
            const int s = tid + i * 256;        // 0..1023
            const int r = s >> 4, c8 = (s & 15) << 3;
            CP_ASYNC16(voff + (uint32_t)(r * AT_V_STRIDE + c8) * 2,
                       Vw + (size_t)r * E_DIM + ec * 128 + c8);
        }
        CP_COMMIT();
    };

    load_v(0, 0);
    for (int ec = 0; ec < 8; ec++) {
        if (ec < 7) { load_v(ec + 1, (ec + 1) & 1); CP_WAIT(1); }
        else        { CP_WAIT(0); }
        __syncthreads();

        const uint32_t vs = sbase + AT_U_OFF + (uint32_t)(ec & 1) * AT_V_STAGE;
        float acc[8][4];
#pragma unroll
        for (int ni = 0; ni < 8; ni++)
#pragma unroll
            for (int j = 0; j < 4; j++) acc[ni][j] = 0.f;

#pragma unroll
        for (int kt = 0; kt < 4; kt++) {
#pragma unroll
            for (int nt4 = 0; nt4 < 4; nt4++) {
                uint32_t b[4];
                LDMATRIX_X4_TRANS(b[0], b[1], b[2], b[3],
                    vs + (uint32_t)((lrow + kt * 16) * AT_V_STRIDE +
                                    wn * 64 + lcol8 + nt4 * 16) * 2);
                mma_fp16(acc[2 * nt4],     pf[kt], &b[0]);
                mma_fp16(acc[2 * nt4 + 1], pf[kt], &b[2]);
            }
        }

#pragma unroll
        for (int ni = 0; ni < 8; ni++) {
            const int row = wm * 16 + g;
            const int col = ec * 128 + wn * 64 + ni * 8 + t * 2;
            *(float2*)(Ow + (size_t)row * E_DIM + col) =
                make_float2(acc[ni][0], acc[ni][1]);
            *(float2*)(Ow + (size_t)(row + 8) * E_DIM + col) =
                make_float2(acc[ni][2], acc[ni][3]);
        }
        __syncthreads();
    }
}

// ---------------------------------------------------------------------------
// out = LayerNorm(A + B) * g + be; optionally also out_h = f16(out)
// ---------------------------------------------------------------------------
template<int DUAL>
__global__ __launch_bounds__(256)
void add_ln(const float* __restrict__ A, const float* __restrict__ B,
            const float* __restrict__ g, const float* __restrict__ be,
            float* __restrict__ out, __half* __restrict__ out_h)
{
    const int row = blockIdx.x;
    const int tid = threadIdx.x;
    const int col = tid << 2;

    const float4 a = *(const float4*)(A + (size_t)row * E_DIM + col);
    const float4 b = *(const float4*)(B + (size_t)row * E_DIM + col);
    float v0 = a.x + b.x, v1 = a.y + b.y, v2 = a.z + b.z, v3 = a.w + b.w;

    float s  = v0 + v1 + v2 + v3;
    float sq = v0 * v0 + v1 * v1 + v2 * v2 + v3 * v3;
#pragma unroll
    for (int o = 16; o > 0; o >>= 1) {
        s  += __shfl_xor_sync(0xffffffffu, s, o);
        sq += __shfl_xor_sync(0xffffffffu, sq, o);
    }
    __shared__ float rs[8], rq[8];
    __shared__ float s_mean, s_rstd;
    if ((tid & 31) == 0) { rs[tid >> 5] = s; rq[tid >> 5] = sq; }
    __syncthreads();
    if (tid == 0) {
        float ts = 0.f, tq = 0.f;
#pragma unroll
        for (int i = 0; i < 8; i++) { ts += rs[i]; tq += rq[i]; }
        const float mean = ts * (1.f / E_DIM);
        const float var = tq * (1.f / E_DIM) - mean * mean;
        s_mean = mean;
        s_rstd = rsqrtf(var + 1e-5f);
    }
    __syncthreads();
    const float mean = s_mean, rstd = s_rstd;

    const float4 gg = *(const float4*)(g + col);
    const float4 bb = *(const float4*)(be + col);
    float4 o4;
    o4.x = (v0 - mean) * rstd * gg.x + bb.x;
    o4.y = (v1 - mean) * rstd * gg.y + bb.y;
    o4.z = (v2 - mean) * rstd * gg.z + bb.z;
    o4.w = (v3 - mean) * rstd * gg.w + bb.w;
    *(float4*)(out + (size_t)row * E_DIM + col) = o4;
    if (DUAL) {
        __half2 h0 = __floats2half2_rn(o4.x, o4.y);
        __half2 h1 = __floats2half2_rn(o4.z, o4.w);
        uint2 pk;
        pk.x = *(uint32_t*)&h0;
        pk.y = *(uint32_t*)&h1;
        *(uint2*)(out_h + (size_t)row * E_DIM + col) = pk;
    }
}

// ---------------------------------------------------------------------------
extern "C" void kernel_launch(void* const* d_in, const int* in_sizes, int n_in,
                              void* d_out, int out_size)
{
    const float* x   = (const float*)d_in[0];
    const float* Wq  = (const float*)d_in[1];
    const float* bq  = (const float*)d_in[2];
    const float* Wk  = (const float*)d_in[3];
    const float* bk  = (const float*)d_in[4];
    const float* Wv  = (const float*)d_in[5];
    const float* bv  = (const float*)d_in[6];
    const float* g1  = (const float*)d_in[7];
    const float* be1 = (const float*)d_in[8];
    const float* W1  = (const float*)d_in[9];
    const float* b1  = (const float*)d_in[10];
    const float* W2  = (const float*)d_in[11];
    const float* b2  = (const float*)d_in[12];
    const float* g2  = (const float*)d_in[13];
    const float* be2 = (const float*)d_in[14];
    float* out = (float*)d_out;

    const int M = in_sizes[0] / E_DIM;   // 16384

    float *Ap, *X1p, *Fp;
    __half *Qh, *Kh, *Vh, *xh, *X1h, *Hh, *Wqh, *Wkh, *Wvh, *W1h, *W2h;
    cudaGetSymbolAddress((void**)&Ap,  g_AT);
    cudaGetSymbolAddress((void**)&X1p, g_X1);
    cudaGetSymbolAddress((void**)&Fp,  g_F);
    cudaGetSymbolAddress((void**)&Qh,  g_Qh);
    cudaGetSymbolAddress((void**)&Kh,  g_Kh);
    cudaGetSymbolAddress((void**)&Vh,  g_Vh);
    cudaGetSymbolAddress((void**)&xh,  g_xh);
    cudaGetSymbolAddress((void**)&X1h, g_X1h);
    cudaGetSymbolAddress((void**)&Hh,  g_Hh);
    cudaGetSymbolAddress((void**)&Wqh, g_Wqh);
    cudaGetSymbolAddress((void**)&Wkh, g_Wkh);
    cudaGetSymbolAddress((void**)&Wvh, g_Wvh);
    cudaGetSymbolAddress((void**)&W1h, g_W1h);
    cudaGetSymbolAddress((void**)&W2h, g_W2h);

    cudaFuncSetAttribute(gemm_fp16<0,0>, cudaFuncAttributeMaxDynamicSharedMemorySize, GEMM_SMEM_BYTES);
    cudaFuncSetAttribute(gemm_fp16<0,1>, cudaFuncAttributeMaxDynamicSharedMemorySize, GEMM_SMEM_BYTES);
    cudaFuncSetAttribute(gemm_fp16<1,1>, cudaFuncAttributeMaxDynamicSharedMemorySize, GEMM_SMEM_BYTES);
    cudaFuncSetAttribute(window_attn_mma, cudaFuncAttributeMaxDynamicSharedMemorySize, AT_SMEM);

    const dim3 blk(256);

    // --- fp16 conversion of GEMM operands ---
    {
        const size_t nx = (size_t)M * E_DIM / 4;
        to_half_kernel<<<(unsigned)((nx + 255) / 256), blk>>>(x, xh, nx);
        const size_t nw = (size_t)E_DIM * E_DIM / 4;
        to_half_kernel<<<(unsigned)((nw + 255) / 256), blk>>>(Wq, Wqh, nw);
        to_half_kernel<<<(unsigned)((nw + 255) / 256), blk>>>(Wk, Wkh, nw);
        to_half_kernel<<<(unsigned)((nw + 255) / 256), blk>>>(Wv, Wvh, nw);
        const size_t nf = (size_t)E_DIM * HID_DIM / 4;
        to_half_kernel<<<(unsigned)((nf + 255) / 256), blk>>>(W1, W1h, nf);
        to_half_kernel<<<(unsigned)((nf + 255) / 256), blk>>>(W2, W2h, nf);
    }

    // Merged QKV projection -> fp16 Q/K/V (only consumed by attention)
    GemmOuts qkv;
    qkv.B[0] = Wqh; qkv.B[1] = Wkh; qkv.B[2] = Wvh;
    qkv.bias[0] = bq; qkv.bias[1] = bk; qkv.bias[2] = bv;
    qkv.C[0] = Qh; qkv.C[1] = Kh; qkv.C[2] = Vh;
    gemm_fp16<0,1><<<dim3(E_DIM / 256, M / 128, 3), blk, GEMM_SMEM_BYTES>>>(xh, qkv, M, E_DIM, E_DIM);

    window_attn_mma<<<M / WSZ, blk, AT_SMEM>>>(Qh, Kh, Vh, Ap);
    add_ln<1><<<M, blk>>>(x, Ap, g1, be1, X1p, X1h);

    // FFN1: A = fp16 X1, output H in fp16 (consumed by FFN2)
    GemmOuts f1; f1.B[0] = W1h; f1.bias[0] = b1; f1.C[0] = Hh;
    f1.B[1] = f1.B[2] = W1h; f1.bias[1] = f1.bias[2] = b1; f1.C[1] = f1.C[2] = Hh;
    gemm_fp16<1,1><<<dim3(HID_DIM / 256, M / 128, 1), blk, GEMM_SMEM_BYTES>>>(X1h, f1, M, HID_DIM, E_DIM);

    GemmOuts f2; f2.B[0] = W2h; f2.bias[0] = b2; f2.C[0] = Fp;
    f2.B[1] = f2.B[2] = W2h; f2.bias[1] = f2.bias[2] = b2; f2.C[1] = f2.C[2] = Fp;
    gemm_fp16<0,0><<<dim3(E_DIM / 256, M / 128, 1), blk, GEMM_SMEM_BYTES>>>(Hh, f2, M, E_DIM, HID_DIM);

    add_ln<0><<<M, blk>>>(X1p, Fp, g2, be2, out, nullptr);
}

// round 9
// speedup vs baseline: 1.2277x; 1.2277x over previous
#include <cuda_runtime.h>
#include <cuda_fp16.h>
#include <cstdint>
#include <math.h>

// ---------------------------------------------------------------------------
// Problem constants
// ---------------------------------------------------------------------------
#define E_DIM   1024
#define HID_DIM 4096
#define WSZ     64
#define M_TOK   16384

// ---------------------------------------------------------------------------
// Scratch (__device__ globals; no allocation allowed)
// ---------------------------------------------------------------------------
__device__ float  g_AT [M_TOK * E_DIM];
__device__ float  g_X1 [M_TOK * E_DIM];
__device__ float  g_F  [M_TOK * E_DIM];
__device__ __half g_Qh [M_TOK * E_DIM];
__device__ __half g_Kh [M_TOK * E_DIM];
__device__ __half g_Vh [M_TOK * E_DIM];
__device__ __half g_xh [M_TOK * E_DIM];
__device__ __half g_X1h[M_TOK * E_DIM];
__device__ __half g_Hh [(size_t)M_TOK * HID_DIM];
__device__ __half g_Wqh[E_DIM * E_DIM];
__device__ __half g_Wkh[E_DIM * E_DIM];
__device__ __half g_Wvh[E_DIM * E_DIM];
__device__ __half g_W1h[(size_t)E_DIM * HID_DIM];
__device__ __half g_W2h[(size_t)E_DIM * HID_DIM];

// ---------------------------------------------------------------------------
// PTX helpers
// ---------------------------------------------------------------------------
__device__ __forceinline__ uint32_t smem_to_u32(const void* p) {
    uint32_t a;
    asm("{ .reg .u64 t; cvta.to.shared.u64 t, %1; cvt.u32.u64 %0, t; }"
        : "=r"(a) : "l"(p));
    return a;
}

#define CP_ASYNC16(saddr, gptr) \
    asm volatile("cp.async.cg.shared.global [%0], [%1], 16;" \
                 :: "r"(saddr), "l"(gptr))
#define CP_COMMIT() asm volatile("cp.async.commit_group;" ::: "memory")
#define CP_WAIT(n)  asm volatile("cp.async.wait_group %0;" :: "n"(n) : "memory")

#define LDMATRIX_X4(r0, r1, r2, r3, addr) \
    asm volatile("ldmatrix.sync.aligned.m8n8.x4.shared.b16 {%0,%1,%2,%3}, [%4];" \
                 : "=r"(r0), "=r"(r1), "=r"(r2), "=r"(r3) : "r"(addr))

#define LDMATRIX_X4_TRANS(r0, r1, r2, r3, addr) \
    asm volatile("ldmatrix.sync.aligned.m8n8.x4.trans.shared.b16 {%0,%1,%2,%3}, [%4];" \
                 : "=r"(r0), "=r"(r1), "=r"(r2), "=r"(r3) : "r"(addr))

__device__ __forceinline__ void mma_fp16(float* c, const uint32_t* a, const uint32_t* b) {
    asm volatile(
        "mma.sync.aligned.m16n8k16.row.col.f32.f16.f16.f32 "
        "{%0,%1,%2,%3}, {%4,%5,%6,%7}, {%8,%9}, {%0,%1,%2,%3};"
        : "+f"(c[0]), "+f"(c[1]), "+f"(c[2]), "+f"(c[3])
        : "r"(a[0]), "r"(a[1]), "r"(a[2]), "r"(a[3]), "r"(b[0]), "r"(b[1]));
}

// ---------------------------------------------------------------------------
// Elementwise f32 -> f16 conversion
// ---------------------------------------------------------------------------
__global__ __launch_bounds__(256)
void to_half_kernel(const float* __restrict__ in, __half* __restrict__ out, size_t n4)
{
    const size_t i = (size_t)blockIdx.x * 256 + threadIdx.x;
    if (i >= n4) return;
    const float4 v = ((const float4*)in)[i];
    __half2 h0 = __floats2half2_rn(v.x, v.y);
    __half2 h1 = __floats2half2_rn(v.z, v.w);
    uint2 pk;
    pk.x = *(uint32_t*)&h0;
    pk.y = *(uint32_t*)&h1;
    ((uint2*)out)[i] = pk;
}

// ---------------------------------------------------------------------------
// fp16 tensor-core GEMM: C[M,N] = A[M,K] @ B[K,N] + bias
// (optional ReLU; OUT_HALF stores fp16). A,B fp16; accum/bias fp32.
// 128x128x32 block tile, 256 threads (4x2 warps, 32x64 warp tile),
// 4-stage cp.async pipeline with ONE barrier per mainloop iteration,
// ldmatrix fragment loads, 2 CTAs/SM.
// blockIdx.z selects among up to 3 (B, bias, C) triples sharing A.
// ---------------------------------------------------------------------------
#define A_STRIDE_H 40     // halves per A row (conflict-free ldmatrix)
#define B_STRIDE_H 136    // halves per B row (conflict-free trans ldmatrix)
#define A_TILE_BYTES (128 * A_STRIDE_H * 2)   // 10240
#define B_TILE_BYTES (32 * B_STRIDE_H * 2)    // 8704
#define STAGE_BYTES  (A_TILE_BYTES + B_TILE_BYTES)   // 18944
#define GEMM_SMEM_BYTES (4 * STAGE_BYTES)            // 75776

struct GemmOuts {
    const __half* B[3];
    const float*  bias[3];
    void*         C[3];
};

template<int RELU, int OUT_HALF>
__global__ __launch_bounds__(256, 2)
void gemm_fp16(const __half* __restrict__ A, GemmOuts io,
               int M, int N, int K)
{
    extern __shared__ char smem[];
    const uint32_t sbase = smem_to_u32(smem);

    const int tid = threadIdx.x;
    const int wid = tid >> 5;
    const int lane = tid & 31;
    const int g = lane >> 2;    // 0..7
    const int t = lane & 3;     // 0..3

    const int wm = wid & 3;     // warp row (4) -> 32 rows each
    const int wn = wid >> 2;    // warp col (2) -> 64 cols each

    const int m0 = blockIdx.y * 128;
    const int n0 = blockIdx.x * 128;
    const int z  = blockIdx.z;

    const __half* Bmat = io.B[z];
    const float*  bias = io.bias[z];

    const __half* Ag = A + (size_t)m0 * K;
    const __half* Bg = Bmat + n0;

    // Load one 128x32 A tile + 32x128 B tile (fp16) into the given stage
    auto load_tile = [&](int k0, int stage) {
        const uint32_t aoff = sbase + (uint32_t)stage * STAGE_BYTES;
        const uint32_t boff = aoff + A_TILE_BYTES;
#pragma unroll
        for (int i = 0; i < 2; i++) {
            const int s = tid + i * 256;            // 0..511
            const int r = s >> 2, c8 = (s & 3) << 3;
            CP_ASYNC16(aoff + (uint32_t)(r * A_STRIDE_H + c8) * 2,
                       Ag + (size_t)r * K + k0 + c8);
        }
#pragma unroll
        for (int i = 0; i < 2; i++) {
            const int s = tid + i * 256;            // 0..511
            const int r = s >> 4, c8 = (s & 15) << 3;
            CP_ASYNC16(boff + (uint32_t)(r * B_STRIDE_H + c8) * 2,
                       Bg + (size_t)(k0 + r) * N + c8);
        }
        CP_COMMIT();
    };

    float acc[2][8][4];
#pragma unroll
    for (int mi = 0; mi < 2; mi++)
#pragma unroll
        for (int ni = 0; ni < 8; ni++)
#pragma unroll
            for (int j = 0; j < 4; j++) acc[mi][ni][j] = 0.f;

    const int NK = K >> 5;
    load_tile(0, 0);
    load_tile(32, 1);
    load_tile(64, 2);

    // ldmatrix lane addressing
    const int a_row = wm * 32 + (lane & 7) + ((lane >> 3) & 1) * 8;  // + mi*16
    const int a_col = (lane >> 4) << 3;                              // + kk*16
    const int b_row = (lane & 7) + ((lane >> 3) & 1) * 8;            // + kk*16
    const int b_col = wn * 64 + ((lane >> 4) << 3);                  // + ni4*16

    for (int kt = 0; kt < NK; kt++) {
        CP_WAIT(2);                 // chunk kt's group retired
        __syncthreads();            // all warps done with stage (kt-1)&3 reads

        if (kt + 3 < NK) load_tile((kt + 3) << 5, (kt + 3) & 3);
        else CP_COMMIT();           // keep group count uniform

        const uint32_t sA = sbase + (uint32_t)(kt & 3) * STAGE_BYTES;
        const uint32_t sB = sA + A_TILE_BYTES;

#pragma unroll
        for (int kk = 0; kk < 2; kk++) {
            uint32_t a[2][4];
#pragma unroll
            for (int mi = 0; mi < 2; mi++) {
                const uint32_t addr = sA +
                    (uint32_t)((a_row + mi * 16) * A_STRIDE_H + a_col + kk * 16) * 2;
                LDMATRIX_X4(a[mi][0], a[mi][1], a[mi][2], a[mi][3], addr);
            }
            uint32_t b[4][4];
#pragma unroll
            for (int ni4 = 0; ni4 < 4; ni4++) {
                const uint32_t addr = sB +
                    (uint32_t)((b_row + kk * 16) * B_STRIDE_H + b_col + ni4 * 16) * 2;
                LDMATRIX_X4_TRANS(b[ni4][0], b[ni4][1], b[ni4][2], b[ni4][3], addr);
            }
#pragma unroll
            for (int mi = 0; mi < 2; mi++)
#pragma unroll
                for (int ni = 0; ni < 8; ni++)
                    mma_fp16(acc[mi][ni], a[mi], &b[ni >> 1][(ni & 1) * 2]);
        }
    }

    // Epilogue: bias (+ReLU) and store (fp32 or fp16)
#pragma unroll
    for (int mi = 0; mi < 2; mi++) {
        const int row = m0 + wm * 32 + mi * 16 + g;
#pragma unroll
        for (int ni = 0; ni < 8; ni++) {
            const int col = n0 + wn * 64 + ni * 8 + t * 2;
            const float b0 = bias[col], b1 = bias[col + 1];
            float2 lo = make_float2(acc[mi][ni][0] + b0, acc[mi][ni][1] + b1);
            float2 hi = make_float2(acc[mi][ni][2] + b0, acc[mi][ni][3] + b1);
            if (RELU) {
                lo.x = fmaxf(lo.x, 0.f); lo.y = fmaxf(lo.y, 0.f);
                hi.x = fmaxf(hi.x, 0.f); hi.y = fmaxf(hi.y, 0.f);
            }
            if (OUT_HALF) {
                __half* Ch = (__half*)io.C[z];
                __half2 l2 = __floats2half2_rn(lo.x, lo.y);
                __half2 h2 = __floats2half2_rn(hi.x, hi.y);
                *(__half2*)(Ch + (size_t)row * N + col) = l2;
                *(__half2*)(Ch + (size_t)(row + 8) * N + col) = h2;
            } else {
                float* Cf = (float*)io.C[z];
                *(float2*)(Cf + (size_t)row * N + col) = lo;
                *(float2*)(Cf + (size_t)(row + 8) * N + col) = hi;
            }
        }
    }
}

// ---------------------------------------------------------------------------
// Tensor-core window attention: one block per 64-token window, 8 warps.
// Phase 1: S = Q K^T (fp16 mma, fp32 acc), streamed over K=1024.
// Phase 2: softmax (fp32) -> P fp16 -> O = P V (fp16 mma, fp32 acc).
// ---------------------------------------------------------------------------
#define AT_S_STRIDE 68    // floats
#define AT_P_STRIDE 72    // halves
#define AT_QK_STRIDE 72   // halves
#define AT_V_STRIDE 136   // halves
#define AT_S_OFF 0
#define AT_P_OFF (64 * AT_S_STRIDE * 4)                 // 17408
#define AT_U_OFF (AT_P_OFF + 64 * AT_P_STRIDE * 2)      // 26624
#define AT_Q_BYTES (64 * AT_QK_STRIDE * 2)              // 9216
#define AT_QK_STAGE (2 * AT_Q_BYTES)                    // 18432
#define AT_V_STAGE (64 * AT_V_STRIDE * 2)               // 17408
#define AT_SMEM (AT_U_OFF + 2 * AT_QK_STAGE)            // 63488

__global__ __launch_bounds__(256, 2)
void window_attn_mma(const __half* __restrict__ Qh, const __half* __restrict__ Kh,
                     const __half* __restrict__ Vh, float* __restrict__ O)
{
    extern __shared__ char smem[];
    const uint32_t sbase = smem_to_u32(smem);
    float* Sf = (float*)smem;

    const int tid = threadIdx.x;
    const int wid = tid >> 5;
    const int lane = tid & 31;
    const int g = lane >> 2, t = lane & 3;
    const int wm = wid & 3;     // 4 m-warps x 16 rows
    const int wn = wid >> 2;    // 2 n-warps

    const int w = blockIdx.x;
    const __half* Qw = Qh + (size_t)w * WSZ * E_DIM;
    const __half* Kw = Kh + (size_t)w * WSZ * E_DIM;
    const __half* Vw = Vh + (size_t)w * WSZ * E_DIM;
    float* Ow = O + (size_t)w * WSZ * E_DIM;

    const int lrow  = (lane & 7) + ((lane >> 3) & 1) * 8;  // 0..15
    const int lcol8 = (lane >> 4) << 3;                    // 0 or 8

    // ---- Phase 1: S = Q K^T ----
    auto load_qk = [&](int kc, int st) {
        const uint32_t qoff = sbase + AT_U_OFF + (uint32_t)st * AT_QK_STAGE;
        const uint32_t koff = qoff + AT_Q_BYTES;
#pragma unroll
        for (int i = 0; i < 2; i++) {
            const int s = tid + i * 256;        // 0..511
            const int r = s >> 3, c8 = (s & 7) << 3;
            CP_ASYNC16(qoff + (uint32_t)(r * AT_QK_STRIDE + c8) * 2,
                       Qw + (size_t)r * E_DIM + kc * 64 + c8);
            CP_ASYNC16(koff + (uint32_t)(r * AT_QK_STRIDE + c8) * 2,
                       Kw + (size_t)r * E_DIM + kc * 64 + c8);
        }
        CP_COMMIT();
    };

    float accS[4][4];
#pragma unroll
    for (int nt = 0; nt < 4; nt++)
#pragma unroll
        for (int j = 0; j < 4; j++) accS[nt][j] = 0.f;

    load_qk(0, 0);
    for (int kc = 0; kc < 16; kc++) {
        if (kc < 15) { load_qk(kc + 1, (kc + 1) & 1); CP_WAIT(1); }
        else         { CP_WAIT(0); }
        __syncthreads();

        const uint32_t qs = sbase + AT_U_OFF + (uint32_t)(kc & 1) * AT_QK_STAGE;
        const uint32_t ks = qs + AT_Q_BYTES;

#pragma unroll
        for (int kt = 0; kt < 4; kt++) {
            uint32_t a[4];
            LDMATRIX_X4(a[0], a[1], a[2], a[3],
                qs + (uint32_t)((wm * 16 + lrow) * AT_QK_STRIDE + lcol8 + kt * 16) * 2);
            uint32_t b[2][4];
#pragma unroll
            for (int h = 0; h < 2; h++)
                LDMATRIX_X4(b[h][0], b[h][1], b[h][2], b[h][3],
                    ks + (uint32_t)((wn * 32 + h * 16 + lrow) * AT_QK_STRIDE + lcol8 + kt * 16) * 2);
#pragma unroll
            for (int nt = 0; nt < 4; nt++) {
                uint32_t bf[2] = { b[nt >> 1][nt & 1], b[nt >> 1][(nt & 1) + 2] };
                mma_fp16(accS[nt], a, bf);
            }
        }
        __syncthreads();
    }

    // scale & write S (fp32)
    const float SCALE = 0.03125f;  // 1024^-0.5
#pragma unroll
    for (int nt = 0; nt < 4; nt++) {
        const int row = wm * 16 + g;
        const int col = wn * 32 + nt * 8 + t * 2;
        Sf[row * AT_S_STRIDE + col]           = accS[nt][0] * SCALE;
        Sf[row * AT_S_STRIDE + col + 1]       = accS[nt][1] * SCALE;
        Sf[(row + 8) * AT_S_STRIDE + col]     = accS[nt][2] * SCALE;
        Sf[(row + 8) * AT_S_STRIDE + col + 1] = accS[nt][3] * SCALE;
    }
    __syncthreads();

    // ---- softmax (4 threads per row) -> P fp16 ----
    {
        const int row = tid >> 2;
        const int part = (tid & 3) << 4;
        float vb[16];
        float m = -1e30f;
#pragma unroll
        for (int j = 0; j < 16; j++) {
            vb[j] = Sf[row * AT_S_STRIDE + part + j];
            m = fmaxf(m, vb[j]);
        }
        m = fmaxf(m, __shfl_xor_sync(0xffffffffu, m, 1));
        m = fmaxf(m, __shfl_xor_sync(0xffffffffu, m, 2));
        float s = 0.f;
#pragma unroll
        for (int j = 0; j < 16; j++) { vb[j] = __expf(vb[j] - m); s += vb[j]; }
        s += __shfl_xor_sync(0xffffffffu, s, 1);
        s += __shfl_xor_sync(0xffffffffu, s, 2);
        const float inv = 1.f / s;
        __half* Ph = (__half*)(smem + AT_P_OFF);
#pragma unroll
        for (int j = 0; j < 16; j++)
            Ph[row * AT_P_STRIDE + part + j] = __float2half(vb[j] * inv);
    }
    __syncthreads();

    // ---- Phase 2: O = P V ----
    uint32_t pf[4][4];
#pragma unroll
    for (int kt = 0; kt < 4; kt++)
        LDMATRIX_X4(pf[kt][0], pf[kt][1], pf[kt][2], pf[kt][3],
            sbase + AT_P_OFF +
            (uint32_t)((wm * 16 + lrow) * AT_P_STRIDE + lcol8 + kt * 16) * 2);

    auto load_v = [&](int ec, int st) {
        const uint32_t voff = sbase + AT_U_OFF + (uint32_t)st * AT_V_STAGE;
#pragma unroll
        for (int i = 0; i < 4; i++) {
            const int s = tid + i * 256;        // 0..1023
            const int r = s >> 4, c8 = (s & 15) << 3;
            CP_ASYNC16(voff + (uint32_t)(r * AT_V_STRIDE + c8) * 2,
                       Vw + (size_t)r * E_DIM + ec * 128 + c8);
        }
        CP_COMMIT();
    };

    load_v(0, 0);
    for (int ec = 0; ec < 8; ec++) {
        if (ec < 7) { load_v(ec + 1, (ec + 1) & 1); CP_WAIT(1); }
        else        { CP_WAIT(0); }
        __syncthreads();

        const uint32_t vs = sbase + AT_U_OFF + (uint32_t)(ec & 1) * AT_V_STAGE;
        float acc[8][4];
#pragma unroll
        for (int ni = 0; ni < 8; ni++)
#pragma unroll
            for (int j = 0; j < 4; j++) acc[ni][j] = 0.f;

#pragma unroll
        for (int kt = 0; kt < 4; kt++) {
#pragma unroll
            for (int nt4 = 0; nt4 < 4; nt4++) {
                uint32_t b[4];
                LDMATRIX_X4_TRANS(b[0], b[1], b[2], b[3],
                    vs + (uint32_t)((lrow + kt * 16) * AT_V_STRIDE +
                                    wn * 64 + lcol8 + nt4 * 16) * 2);
                mma_fp16(acc[2 * nt4],     pf[kt], &b[0]);
                mma_fp16(acc[2 * nt4 + 1], pf[kt], &b[2]);
            }
        }

#pragma unroll
        for (int ni = 0; ni < 8; ni++) {
            const int row = wm * 16 + g;
            const int col = ec * 128 + wn * 64 + ni * 8 + t * 2;
            *(float2*)(Ow + (size_t)row * E_DIM + col) =
                make_float2(acc[ni][0], acc[ni][1]);
            *(float2*)(Ow + (size_t)(row + 8) * E_DIM + col) =
                make_float2(acc[ni][2], acc[ni][3]);
        }
        __syncthreads();
    }
}

// ---------------------------------------------------------------------------
// out = LayerNorm(A + B) * g + be; optionally also out_h = f16(out)
// ---------------------------------------------------------------------------
template<int DUAL>
__global__ __launch_bounds__(256)
void add_ln(const float* __restrict__ A, const float* __restrict__ B,
            const float* __restrict__ g, const float* __restrict__ be,
            float* __restrict__ out, __half* __restrict__ out_h)
{
    const int row = blockIdx.x;
    const int tid = threadIdx.x;
    const int col = tid << 2;

    const float4 a = *(const float4*)(A + (size_t)row * E_DIM + col);
    const float4 b = *(const float4*)(B + (size_t)row * E_DIM + col);
    float v0 = a.x + b.x, v1 = a.y + b.y, v2 = a.z + b.z, v3 = a.w + b.w;

    float s  = v0 + v1 + v2 + v3;
    float sq = v0 * v0 + v1 * v1 + v2 * v2 + v3 * v3;
#pragma unroll
    for (int o = 16; o > 0; o >>= 1) {
        s  += __shfl_xor_sync(0xffffffffu, s, o);
        sq += __shfl_xor_sync(0xffffffffu, sq, o);
    }
    __shared__ float rs[8], rq[8];
    __shared__ float s_mean, s_rstd;
    if ((tid & 31) == 0) { rs[tid >> 5] = s; rq[tid >> 5] = sq; }
    __syncthreads();
    if (tid == 0) {
        float ts = 0.f, tq = 0.f;
#pragma unroll
        for (int i = 0; i < 8; i++) { ts += rs[i]; tq += rq[i]; }
        const float mean = ts * (1.f / E_DIM);
        const float var = tq * (1.f / E_DIM) - mean * mean;
        s_mean = mean;
        s_rstd = rsqrtf(var + 1e-5f);
    }
    __syncthreads();
    const float mean = s_mean, rstd = s_rstd;

    const float4 gg = *(const float4*)(g + col);
    const float4 bb = *(const float4*)(be + col);
    float4 o4;
    o4.x = (v0 - mean) * rstd * gg.x + bb.x;
    o4.y = (v1 - mean) * rstd * gg.y + bb.y;
    o4.z = (v2 - mean) * rstd * gg.z + bb.z;
    o4.w = (v3 - mean) * rstd * gg.w + bb.w;
    *(float4*)(out + (size_t)row * E_DIM + col) = o4;
    if (DUAL) {
        __half2 h0 = __floats2half2_rn(o4.x, o4.y);
        __half2 h1 = __floats2half2_rn(o4.z, o4.w);
        uint2 pk;
        pk.x = *(uint32_t*)&h0;
        pk.y = *(uint32_t*)&h1;
        *(uint2*)(out_h + (size_t)row * E_DIM + col) = pk;
    }
}

// ---------------------------------------------------------------------------
extern "C" void kernel_launch(void* const* d_in, const int* in_sizes, int n_in,
                              void* d_out, int out_size)
{
    const float* x   = (const float*)d_in[0];
    const float* Wq  = (const float*)d_in[1];
    const float* bq  = (const float*)d_in[2];
    const float* Wk  = (const float*)d_in[3];
    const float* bk  = (const float*)d_in[4];
    const float* Wv  = (const float*)d_in[5];
    const float* bv  = (const float*)d_in[6];
    const float* g1  = (const float*)d_in[7];
    const float* be1 = (const float*)d_in[8];
    const float* W1  = (const float*)d_in[9];
    const float* b1  = (const float*)d_in[10];
    const float* W2  = (const float*)d_in[11];
    const float* b2  = (const float*)d_in[12];
    const float* g2  = (const float*)d_in[13];
    const float* be2 = (const float*)d_in[14];
    float* out = (float*)d_out;

    const int M = in_sizes[0] / E_DIM;   // 16384

    float *Ap, *X1p, *Fp;
    __half *Qh, *Kh, *Vh, *xh, *X1h, *Hh, *Wqh, *Wkh, *Wvh, *W1h, *W2h;
    cudaGetSymbolAddress((void**)&Ap,  g_AT);
    cudaGetSymbolAddress((void**)&X1p, g_X1);
    cudaGetSymbolAddress((void**)&Fp,  g_F);
    cudaGetSymbolAddress((void**)&Qh,  g_Qh);
    cudaGetSymbolAddress((void**)&Kh,  g_Kh);
    cudaGetSymbolAddress((void**)&Vh,  g_Vh);
    cudaGetSymbolAddress((void**)&xh,  g_xh);
    cudaGetSymbolAddress((void**)&X1h, g_X1h);
    cudaGetSymbolAddress((void**)&Hh,  g_Hh);
    cudaGetSymbolAddress((void**)&Wqh, g_Wqh);
    cudaGetSymbolAddress((void**)&Wkh, g_Wkh);
    cudaGetSymbolAddress((void**)&Wvh, g_Wvh);
    cudaGetSymbolAddress((void**)&W1h, g_W1h);
    cudaGetSymbolAddress((void**)&W2h, g_W2h);

    cudaFuncSetAttribute(gemm_fp16<0,0>, cudaFuncAttributeMaxDynamicSharedMemorySize, GEMM_SMEM_BYTES);
    cudaFuncSetAttribute(gemm_fp16<0,1>, cudaFuncAttributeMaxDynamicSharedMemorySize, GEMM_SMEM_BYTES);
    cudaFuncSetAttribute(gemm_fp16<1,1>, cudaFuncAttributeMaxDynamicSharedMemorySize, GEMM_SMEM_BYTES);
    cudaFuncSetAttribute(window_attn_mma, cudaFuncAttributeMaxDynamicSharedMemorySize, AT_SMEM);

    const dim3 blk(256);

    // --- fp16 conversion of GEMM operands ---
    {
        const size_t nx = (size_t)M * E_DIM / 4;
        to_half_kernel<<<(unsigned)((nx + 255) / 256), blk>>>(x, xh, nx);
        const size_t nw = (size_t)E_DIM * E_DIM / 4;
        to_half_kernel<<<(unsigned)((nw + 255) / 256), blk>>>(Wq, Wqh, nw);
        to_half_kernel<<<(unsigned)((nw + 255) / 256), blk>>>(Wk, Wkh, nw);
        to_half_kernel<<<(unsigned)((nw + 255) / 256), blk>>>(Wv, Wvh, nw);
        const size_t nf = (size_t)E_DIM * HID_DIM / 4;
        to_half_kernel<<<(unsigned)((nf + 255) / 256), blk>>>(W1, W1h, nf);
        to_half_kernel<<<(unsigned)((nf + 255) / 256), blk>>>(W2, W2h, nf);
    }

    // Merged QKV projection -> fp16 Q/K/V (only consumed by attention)
    GemmOuts qkv;
    qkv.B[0] = Wqh; qkv.B[1] = Wkh; qkv.B[2] = Wvh;
    qkv.bias[0] = bq; qkv.bias[1] = bk; qkv.bias[2] = bv;
    qkv.C[0] = Qh; qkv.C[1] = Kh; qkv.C[2] = Vh;
    gemm_fp16<0,1><<<dim3(E_DIM / 128, M / 128, 3), blk, GEMM_SMEM_BYTES>>>(xh, qkv, M, E_DIM, E_DIM);

    window_attn_mma<<<M / WSZ, blk, AT_SMEM>>>(Qh, Kh, Vh, Ap);
    add_ln<1><<<M, blk>>>(x, Ap, g1, be1, X1p, X1h);

    // FFN1: A = fp16 X1, output H in fp16 (consumed by FFN2)
    GemmOuts f1; f1.B[0] = W1h; f1.bias[0] = b1; f1.C[0] = Hh;
    f1.B[1] = f1.B[2] = W1h; f1.bias[1] = f1.bias[2] = b1; f1.C[1] = f1.C[2] = Hh;
    gemm_fp16<1,1><<<dim3(HID_DIM / 128, M / 128, 1), blk, GEMM_SMEM_BYTES>>>(X1h, f1, M, HID_DIM, E_DIM);

    GemmOuts f2; f2.B[0] = W2h; f2.bias[0] = b2; f2.C[0] = Fp;
    f2.B[1] = f2.B[2] = W2h; f2.bias[1] = f2.bias[2] = b2; f2.C[1] = f2.C[2] = Fp;
    gemm_fp16<0,0><<<dim3(E_DIM / 128, M / 128, 1), blk, GEMM_SMEM_BYTES>>>(Hh, f2, M, E_DIM, HID_DIM);

    add_ln<0><<<M, blk>>>(X1p, Fp, g2, be2, out, nullptr);
}

// round 10
// speedup vs baseline: 1.2915x; 1.0520x over previous
#include <cuda_runtime.h>
#include <cuda_fp16.h>
#include <cstdint>
#include <math.h>

// ---------------------------------------------------------------------------
// Problem constants
// ---------------------------------------------------------------------------
#define E_DIM   1024
#define HID_DIM 4096
#define WSZ     64
#define M_TOK   16384

// ---------------------------------------------------------------------------
// Scratch (__device__ globals; no allocation allowed)
// ---------------------------------------------------------------------------
__device__ float  g_AT [M_TOK * E_DIM];
__device__ float  g_X1 [M_TOK * E_DIM];
__device__ float  g_F  [M_TOK * E_DIM];
__device__ __half g_Qh [M_TOK * E_DIM];
__device__ __half g_Kh [M_TOK * E_DIM];
__device__ __half g_Vh [M_TOK * E_DIM];
__device__ __half g_xh [M_TOK * E_DIM];
__device__ __half g_X1h[M_TOK * E_DIM];
__device__ __half g_Hh [(size_t)M_TOK * HID_DIM];
__device__ __half g_Wqh[E_DIM * E_DIM];
__device__ __half g_Wkh[E_DIM * E_DIM];
__device__ __half g_Wvh[E_DIM * E_DIM];
__device__ __half g_W1h[(size_t)E_DIM * HID_DIM];
__device__ __half g_W2h[(size_t)E_DIM * HID_DIM];

// ---------------------------------------------------------------------------
// PTX helpers
// ---------------------------------------------------------------------------
__device__ __forceinline__ uint32_t smem_to_u32(const void* p) {
    uint32_t a;
    asm("{ .reg .u64 t; cvta.to.shared.u64 t, %1; cvt.u32.u64 %0, t; }"
        : "=r"(a) : "l"(p));
    return a;
}

#define CP_ASYNC16(saddr, gptr) \
    asm volatile("cp.async.cg.shared.global [%0], [%1], 16;" \
                 :: "r"(saddr), "l"(gptr))
#define CP_COMMIT() asm volatile("cp.async.commit_group;" ::: "memory")
#define CP_WAIT(n)  asm volatile("cp.async.wait_group %0;" :: "n"(n) : "memory")

#define LDMATRIX_X4(r0, r1, r2, r3, addr) \
    asm volatile("ldmatrix.sync.aligned.m8n8.x4.shared.b16 {%0,%1,%2,%3}, [%4];" \
                 : "=r"(r0), "=r"(r1), "=r"(r2), "=r"(r3) : "r"(addr))

#define LDMATRIX_X4_TRANS(r0, r1, r2, r3, addr) \
    asm volatile("ldmatrix.sync.aligned.m8n8.x4.trans.shared.b16 {%0,%1,%2,%3}, [%4];" \
                 : "=r"(r0), "=r"(r1), "=r"(r2), "=r"(r3) : "r"(addr))

__device__ __forceinline__ void mma_fp16(float* c, const uint32_t* a, const uint32_t* b) {
    asm volatile(
        "mma.sync.aligned.m16n8k16.row.col.f32.f16.f16.f32 "
        "{%0,%1,%2,%3}, {%4,%5,%6,%7}, {%8,%9}, {%0,%1,%2,%3};"
        : "+f"(c[0]), "+f"(c[1]), "+f"(c[2]), "+f"(c[3])
        : "r"(a[0]), "r"(a[1]), "r"(a[2]), "r"(a[3]), "r"(b[0]), "r"(b[1]));
}

// ---------------------------------------------------------------------------
// Elementwise f32 -> f16 conversion
// ---------------------------------------------------------------------------
__global__ __launch_bounds__(256)
void to_half_kernel(const float* __restrict__ in, __half* __restrict__ out, size_t n4)
{
    const size_t i = (size_t)blockIdx.x * 256 + threadIdx.x;
    if (i >= n4) return;
    const float4 v = ((const float4*)in)[i];
    __half2 h0 = __floats2half2_rn(v.x, v.y);
    __half2 h1 = __floats2half2_rn(v.z, v.w);
    uint2 pk;
    pk.x = *(uint32_t*)&h0;
    pk.y = *(uint32_t*)&h1;
    ((uint2*)out)[i] = pk;
}

// ---------------------------------------------------------------------------
// fp16 tensor-core GEMM: C[M,N] = A[M,K] @ B[K,N] + bias
// (optional ReLU; OUT_HALF stores fp16). A,B fp16; accum/bias fp32.
// 128x128x64 block tile, 256 threads (4x2 warps, 32x64 warp tile),
// 3-stage cp.async pipeline (BK=64) with ONE barrier per iteration,
// ldmatrix fragment loads, 2 CTAs/SM.
// blockIdx.z selects among up to 3 (B, bias, C) triples sharing A.
// ---------------------------------------------------------------------------
#define A_STRIDE_H 72     // halves per A row (64 + 8 pad, conflict-free ldmatrix)
#define B_STRIDE_H 136    // halves per B row (conflict-free trans ldmatrix)
#define A_TILE_BYTES (128 * A_STRIDE_H * 2)   // 18432
#define B_TILE_BYTES (64 * B_STRIDE_H * 2)    // 17408
#define STAGE_BYTES  (A_TILE_BYTES + B_TILE_BYTES)   // 35840
#define GEMM_SMEM_BYTES (3 * STAGE_BYTES)            // 107520

struct GemmOuts {
    const __half* B[3];
    const float*  bias[3];
    void*         C[3];
};

template<int RELU, int OUT_HALF>
__global__ __launch_bounds__(256, 2)
void gemm_fp16(const __half* __restrict__ A, GemmOuts io,
               int M, int N, int K)
{
    extern __shared__ char smem[];
    const uint32_t sbase = smem_to_u32(smem);

    const int tid = threadIdx.x;
    const int wid = tid >> 5;
    const int lane = tid & 31;
    const int g = lane >> 2;    // 0..7
    const int t = lane & 3;     // 0..3

    const int wm = wid & 3;     // warp row (4) -> 32 rows each
    const int wn = wid >> 2;    // warp col (2) -> 64 cols each

    const int m0 = blockIdx.y * 128;
    const int n0 = blockIdx.x * 128;
    const int z  = blockIdx.z;

    const __half* Bmat = io.B[z];
    const float*  bias = io.bias[z];

    const __half* Ag = A + (size_t)m0 * K;
    const __half* Bg = Bmat + n0;

    // Load one 128x64 A tile + 64x128 B tile (fp16) into the given stage
    auto load_tile = [&](int k0, int stage) {
        const uint32_t aoff = sbase + (uint32_t)stage * STAGE_BYTES;
        const uint32_t boff = aoff + A_TILE_BYTES;
#pragma unroll
        for (int i = 0; i < 4; i++) {
            const int s = tid + i * 256;            // 0..1023
            const int r = s >> 3, c8 = (s & 7) << 3;
            CP_ASYNC16(aoff + (uint32_t)(r * A_STRIDE_H + c8) * 2,
                       Ag + (size_t)r * K + k0 + c8);
        }
#pragma unroll
        for (int i = 0; i < 4; i++) {
            const int s = tid + i * 256;            // 0..1023
            const int r = s >> 4, c8 = (s & 15) << 3;
            CP_ASYNC16(boff + (uint32_t)(r * B_STRIDE_H + c8) * 2,
                       Bg + (size_t)(k0 + r) * N + c8);
        }
        CP_COMMIT();
    };

    float acc[2][8][4];
#pragma unroll
    for (int mi = 0; mi < 2; mi++)
#pragma unroll
        for (int ni = 0; ni < 8; ni++)
#pragma unroll
            for (int j = 0; j < 4; j++) acc[mi][ni][j] = 0.f;

    const int NK = K >> 6;
    load_tile(0, 0);
    load_tile(64, 1);

    // ldmatrix lane addressing
    const int a_row = wm * 32 + (lane & 7) + ((lane >> 3) & 1) * 8;  // + mi*16
    const int a_col = (lane >> 4) << 3;                              // + kk*16
    const int b_row = (lane & 7) + ((lane >> 3) & 1) * 8;            // + kk*16
    const int b_col = wn * 64 + ((lane >> 4) << 3);                  // + ni4*16

    for (int kt = 0; kt < NK; kt++) {
        CP_WAIT(1);                 // chunk kt's group retired
        __syncthreads();            // all warps done reading stage (kt-1)%3

        if (kt + 2 < NK) load_tile((kt + 2) << 6, (kt + 2) % 3);
        else CP_COMMIT();           // keep group count uniform

        const uint32_t sA = sbase + (uint32_t)(kt % 3) * STAGE_BYTES;
        const uint32_t sB = sA + A_TILE_BYTES;

#pragma unroll
        for (int kk = 0; kk < 4; kk++) {
            uint32_t a[2][4];
#pragma unroll
            for (int mi = 0; mi < 2; mi++) {
                const uint32_t addr = sA +
                    (uint32_t)((a_row + mi * 16) * A_STRIDE_H + a_col + kk * 16) * 2;
                LDMATRIX_X4(a[mi][0], a[mi][1], a[mi][2], a[mi][3], addr);
            }
            uint32_t b[4][4];
#pragma unroll
            for (int ni4 = 0; ni4 < 4; ni4++) {
                const uint32_t addr = sB +
                    (uint32_t)((b_row + kk * 16) * B_STRIDE_H + b_col + ni4 * 16) * 2;
                LDMATRIX_X4_TRANS(b[ni4][0], b[ni4][1], b[ni4][2], b[ni4][3], addr);
            }
#pragma unroll
            for (int mi = 0; mi < 2; mi++)
#pragma unroll
                for (int ni = 0; ni < 8; ni++)
                    mma_fp16(acc[mi][ni], a[mi], &b[ni >> 1][(ni & 1) * 2]);
        }
    }

    // Epilogue: bias (+ReLU) and store (fp32 or fp16)
#pragma unroll
    for (int mi = 0; mi < 2; mi++) {
        const int row = m0 + wm * 32 + mi * 16 + g;
#pragma unroll
        for (int ni = 0; ni < 8; ni++) {
            const int col = n0 + wn * 64 + ni * 8 + t * 2;
            const float b0 = bias[col], b1 = bias[col + 1];
            float2 lo = make_float2(acc[mi][ni][0] + b0, acc[mi][ni][1] + b1);
            float2 hi = make_float2(acc[mi][ni][2] + b0, acc[mi][ni][3] + b1);
            if (RELU) {
                lo.x = fmaxf(lo.x, 0.f); lo.y = fmaxf(lo.y, 0.f);
                hi.x = fmaxf(hi.x, 0.f); hi.y = fmaxf(hi.y, 0.f);
            }
            if (OUT_HALF) {
                __half* Ch = (__half*)io.C[z];
                __half2 l2 = __floats2half2_rn(lo.x, lo.y);
                __half2 h2 = __floats2half2_rn(hi.x, hi.y);
                *(__half2*)(Ch + (size_t)row * N + col) = l2;
                *(__half2*)(Ch + (size_t)(row + 8) * N + col) = h2;
            } else {
                float* Cf = (float*)io.C[z];
                *(float2*)(Cf + (size_t)row * N + col) = lo;
                *(float2*)(Cf + (size_t)(row + 8) * N + col) = hi;
            }
        }
    }
}

// ---------------------------------------------------------------------------
// Tensor-core window attention: one block per 64-token window, 8 warps.
// Phase 1: S = Q K^T (fp16 mma, fp32 acc), streamed over K=1024.
// Phase 2: softmax (fp32) -> P fp16 -> O = P V (fp16 mma, fp32 acc).
// ---------------------------------------------------------------------------
#define AT_S_STRIDE 68    // floats
#define AT_P_STRIDE 72    // halves
#define AT_QK_STRIDE 72   // halves
#define AT_V_STRIDE 136   // halves
#define AT_S_OFF 0
#define AT_P_OFF (64 * AT_S_STRIDE * 4)                 // 17408
#define AT_U_OFF (AT_P_OFF + 64 * AT_P_STRIDE * 2)      // 26624
#define AT_Q_BYTES (64 * AT_QK_STRIDE * 2)              // 9216
#define AT_QK_STAGE (2 * AT_Q_BYTES)                    // 18432
#define AT_V_STAGE (64 * AT_V_STRIDE * 2)               // 17408
#define AT_SMEM (AT_U_OFF + 2 * AT_QK_STAGE)            // 63488

__global__ __launch_bounds__(256, 2)
void window_attn_mma(const __half* __restrict__ Qh, const __half* __restrict__ Kh,
                     const __half* __restrict__ Vh, float* __restrict__ O)
{
    extern __shared__ char smem[];
    const uint32_t sbase = smem_to_u32(smem);
    float* Sf = (float*)smem;

    const int tid = threadIdx.x;
    const int wid = tid >> 5;
    const int lane = tid & 31;
    const int g = lane >> 2, t = lane & 3;
    const int wm = wid & 3;     // 4 m-warps x 16 rows
    const int wn = wid >> 2;    // 2 n-warps

    const int w = blockIdx.x;
    const __half* Qw = Qh + (size_t)w * WSZ * E_DIM;
    const __half* Kw = Kh + (size_t)w * WSZ * E_DIM;
    const __half* Vw = Vh + (size_t)w * WSZ * E_DIM;
    float* Ow = O + (size_t)w * WSZ * E_DIM;

    const int lrow  = (lane & 7) + ((lane >> 3) & 1) * 8;  // 0..15
    const int lcol8 = (lane >> 4) << 3;                    // 0 or 8

    // ---- Phase 1: S = Q K^T ----
    auto load_qk = [&](int kc, int st) {
        const uint32_t qoff = sbase + AT_U_OFF + (uint32_t)st * AT_QK_STAGE;
        const uint32_t koff = qoff + AT_Q_BYTES;
#pragma unroll
        for (int i = 0; i < 2; i++) {
            const int s = tid + i * 256;        // 0..511
            const int r = s >> 3, c8 = (s & 7) << 3;
            CP_ASYNC16(qoff + (uint32_t)(r * AT_QK_STRIDE + c8) * 2,
                       Qw + (size_t)r * E_DIM + kc * 64 + c8);
            CP_ASYNC16(koff + (uint32_t)(r * AT_QK_STRIDE + c8) * 2,
                       Kw + (size_t)r * E_DIM + kc * 64 + c8);
        }
        CP_COMMIT();
    };

    float accS[4][4];
#pragma unroll
    for (int nt = 0; nt < 4; nt++)
#pragma unroll
        for (int j = 0; j < 4; j++) accS[nt][j] = 0.f;

    load_qk(0, 0);
    for (int kc = 0; kc < 16; kc++) {
        if (kc < 15) { load_qk(kc + 1, (kc + 1) & 1); CP_WAIT(1); }
        else         { CP_WAIT(0); }
        __syncthreads();

        const uint32_t qs = sbase + AT_U_OFF + (uint32_t)(kc & 1) * AT_QK_STAGE;
        const uint32_t ks = qs + AT_Q_BYTES;

#pragma unroll
        for (int kt = 0; kt < 4; kt++) {
            uint32_t a[4];
            LDMATRIX_X4(a[0], a[1], a[2], a[3],
                qs + (uint32_t)((wm * 16 + lrow) * AT_QK_STRIDE + lcol8 + kt * 16) * 2);
            uint32_t b[2][4];
#pragma unroll
            for (int h = 0; h < 2; h++)
                LDMATRIX_X4(b[h][0], b[h][1], b[h][2], b[h][3],
                    ks + (uint32_t)((wn * 32 + h * 16 + lrow) * AT_QK_STRIDE + lcol8 + kt * 16) * 2);
#pragma unroll
            for (int nt = 0; nt < 4; nt++) {
                uint32_t bf[2] = { b[nt >> 1][nt & 1], b[nt >> 1][(nt & 1) + 2] };
                mma_fp16(accS[nt], a, bf);
            }
        }
        __syncthreads();
    }

    // scale & write S (fp32)
    const float SCALE = 0.03125f;  // 1024^-0.5
#pragma unroll
    for (int nt = 0; nt < 4; nt++) {
        const int row = wm * 16 + g;
        const int col = wn * 32 + nt * 8 + t * 2;
        Sf[row * AT_S_STRIDE + col]           = accS[nt][0] * SCALE;
        Sf[row * AT_S_STRIDE + col + 1]       = accS[nt][1] * SCALE;
        Sf[(row + 8) * AT_S_STRIDE + col]     = accS[nt][2] * SCALE;
        Sf[(row + 8) * AT_S_STRIDE + col + 1] = accS[nt][3] * SCALE;
    }
    __syncthreads();

    // ---- softmax (4 threads per row) -> P fp16 ----
    {
        const int row = tid >> 2;
        const int part = (tid & 3) << 4;
        float vb[16];
        float m = -1e30f;
#pragma unroll
        for (int j = 0; j < 16; j++) {
            vb[j] = Sf[row * AT_S_STRIDE + part + j];
            m = fmaxf(m, vb[j]);
        }
        m = fmaxf(m, __shfl_xor_sync(0xffffffffu, m, 1));
        m = fmaxf(m, __shfl_xor_sync(0xffffffffu, m, 2));
        float s = 0.f;
#pragma unroll
        for (int j = 0; j < 16; j++) { vb[j] = __expf(vb[j] - m); s += vb[j]; }
        s += __shfl_xor_sync(0xffffffffu, s, 1);
        s += __shfl_xor_sync(0xffffffffu, s, 2);
        const float inv = 1.f / s;
        __half* Ph = (__half*)(smem + AT_P_OFF);
#pragma unroll
        for (int j = 0; j < 16; j++)
            Ph[row * AT_P_STRIDE + part + j] = __float2half(vb[j] * inv);
    }
    __syncthreads();

    // ---- Phase 2: O = P V ----
    uint32_t pf[4][4];
#pragma unroll
    for (int kt = 0; kt < 4; kt++)
        LDMATRIX_X4(pf[kt][0], pf[kt][1], pf[kt][2], pf[kt][3],
            sbase + AT_P_OFF +
            (uint32_t)((wm * 16 + lrow) * AT_P_STRIDE + lcol8 + kt * 16) * 2);

    auto load_v = [&](int ec, int st) {
        const uint32_t voff = sbase + AT_U_OFF + (uint32_t)st * AT_V_STAGE;
#pragma unroll
        for (int i = 0; i < 4; i++) {
            const int s = tid + i * 256;        // 0..1023
            const int r = s >> 4, c8 = (s & 15) << 3;
            CP_ASYNC16(voff + (uint32_t)(r * AT_V_STRIDE + c8) * 2,
                       Vw + (size_t)r * E_DIM + ec * 128 + c8);
        }
        CP_COMMIT();
    };

    load_v(0, 0);
    for (int ec = 0; ec < 8; ec++) {
        if (ec < 7) { load_v(ec + 1, (ec + 1) & 1); CP_WAIT(1); }
        else        { CP_WAIT(0); }
        __syncthreads();

        const uint32_t vs = sbase + AT_U_OFF + (uint32_t)(ec & 1) * AT_V_STAGE;
        float acc[8][4];
#pragma unroll
        for (int ni = 0; ni < 8; ni++)
#pragma unroll
            for (int j = 0; j < 4; j++) acc[ni][j] = 0.f;

#pragma unroll
        for (int kt = 0; kt < 4; kt++) {
#pragma unroll
            for (int nt4 = 0; nt4 < 4; nt4++) {
                uint32_t b[4];
                LDMATRIX_X4_TRANS(b[0], b[1], b[2], b[3],
                    vs + (uint32_t)((lrow + kt * 16) * AT_V_STRIDE +
                                    wn * 64 + lcol8 + nt4 * 16) * 2);
                mma_fp16(acc[2 * nt4],     pf[kt], &b[0]);
                mma_fp16(acc[2 * nt4 + 1], pf[kt], &b[2]);
            }
        }

#pragma unroll
        for (int ni = 0; ni < 8; ni++) {
            const int row = wm * 16 + g;
            const int col = ec * 128 + wn * 64 + ni * 8 + t * 2;
            *(float2*)(Ow + (size_t)row * E_DIM + col) =
                make_float2(acc[ni][0], acc[ni][1]);
            *(float2*)(Ow + (size_t)(row + 8) * E_DIM + col) =
                make_float2(acc[ni][2], acc[ni][3]);
        }
        __syncthreads();
    }
}

// ---------------------------------------------------------------------------
// out = LayerNorm(A + B) * g + be; optionally also out_h = f16(out)
// ---------------------------------------------------------------------------
template<int DUAL>
__global__ __launch_bounds__(256)
void add_ln(const float* __restrict__ A, const float* __restrict__ B,
            const float* __restrict__ g, const float* __restrict__ be,
            float* __restrict__ out, __half* __restrict__ out_h)
{
    const int row = blockIdx.x;
    const int tid = threadIdx.x;
    const int col = tid << 2;

    const float4 a = *(const float4*)(A + (size_t)row * E_DIM + col);
    const float4 b = *(const float4*)(B + (size_t)row * E_DIM + col);
    float v0 = a.x + b.x, v1 = a.y + b.y, v2 = a.z + b.z, v3 = a.w + b.w;

    float s  = v0 + v1 + v2 + v3;
    float sq = v0 * v0 + v1 * v1 + v2 * v2 + v3 * v3;
#pragma unroll
    for (int o = 16; o > 0; o >>= 1) {
        s  += __shfl_xor_sync(0xffffffffu, s, o);
        sq += __shfl_xor_sync(0xffffffffu, sq, o);
    }
    __shared__ float rs[8], rq[8];
    __shared__ float s_mean, s_rstd;
    if ((tid & 31) == 0) { rs[tid >> 5] = s; rq[tid >> 5] = sq; }
    __syncthreads();
    if (tid == 0) {
        float ts = 0.f, tq = 0.f;
#pragma unroll
        for (int i = 0; i < 8; i++) { ts += rs[i]; tq += rq[i]; }
        const float mean = ts * (1.f / E_DIM);
        const float var = tq * (1.f / E_DIM) - mean * mean;
        s_mean = mean;
        s_rstd = rsqrtf(var + 1e-5f);
    }
    __syncthreads();
    const float mean = s_mean, rstd = s_rstd;

    const float4 gg = *(const float4*)(g + col);
    const float4 bb = *(const float4*)(be + col);
    float4 o4;
    o4.x = (v0 - mean) * rstd * gg.x + bb.x;
    o4.y = (v1 - mean) * rstd * gg.y + bb.y;
    o4.z = (v2 - mean) * rstd * gg.z + bb.z;
    o4.w = (v3 - mean) * rstd * gg.w + bb.w;
    *(float4*)(out + (size_t)row * E_DIM + col) = o4;
    if (DUAL) {
        __half2 h0 = __floats2half2_rn(o4.x, o4.y);
        __half2 h1 = __floats2half2_rn(o4.z, o4.w);
        uint2 pk;
        pk.x = *(uint32_t*)&h0;
        pk.y = *(uint32_t*)&h1;
        *(uint2*)(out_h + (size_t)row * E_DIM + col) = pk;
    }
}

// ---------------------------------------------------------------------------
extern "C" void kernel_launch(void* const* d_in, const int* in_sizes, int n_in,
                              void* d_out, int out_size)
{
    const float* x   = (const float*)d_in[0];
    const float* Wq  = (const float*)d_in[1];
    const float* bq  = (const float*)d_in[2];
    const float* Wk  = (const float*)d_in[3];
    const float* bk  = (const float*)d_in[4];
    const float* Wv  = (const float*)d_in[5];
    const float* bv  = (const float*)d_in[6];
    const float* g1  = (const float*)d_in[7];
    const float* be1 = (const float*)d_in[8];
    const float* W1  = (const float*)d_in[9];
    const float* b1  = (const float*)d_in[10];
    const float* W2  = (const float*)d_in[11];
    const float* b2  = (const float*)d_in[12];
    const float* g2  = (const float*)d_in[13];
    const float* be2 = (const float*)d_in[14];
    float* out = (float*)d_out;

    const int M = in_sizes[0] / E_DIM;   // 16384

    float *Ap, *X1p, *Fp;
    __half *Qh, *Kh, *Vh, *xh, *X1h, *Hh, *Wqh, *Wkh, *Wvh, *W1h, *W2h;
    cudaGetSymbolAddress((void**)&Ap,  g_AT);
    cudaGetSymbolAddress((void**)&X1p, g_X1);
    cudaGetSymbolAddress((void**)&Fp,  g_F);
    cudaGetSymbolAddress((void**)&Qh,  g_Qh);
    cudaGetSymbolAddress((void**)&Kh,  g_Kh);
    cudaGetSymbolAddress((void**)&Vh,  g_Vh);
    cudaGetSymbolAddress((void**)&xh,  g_xh);
    cudaGetSymbolAddress((void**)&X1h, g_X1h);
    cudaGetSymbolAddress((void**)&Hh,  g_Hh);
    cudaGetSymbolAddress((void**)&Wqh, g_Wqh);
    cudaGetSymbolAddress((void**)&Wkh, g_Wkh);
    cudaGetSymbolAddress((void**)&Wvh, g_Wvh);
    cudaGetSymbolAddress((void**)&W1h, g_W1h);
    cudaGetSymbolAddress((void**)&W2h, g_W2h);

    cudaFuncSetAttribute(gemm_fp16<0,0>, cudaFuncAttributeMaxDynamicSharedMemorySize, GEMM_SMEM_BYTES);
    cudaFuncSetAttribute(gemm_fp16<0,1>, cudaFuncAttributeMaxDynamicSharedMemorySize, GEMM_SMEM_BYTES);
    cudaFuncSetAttribute(gemm_fp16<1,1>, cudaFuncAttributeMaxDynamicSharedMemorySize, GEMM_SMEM_BYTES);
    cudaFuncSetAttribute(window_attn_mma, cudaFuncAttributeMaxDynamicSharedMemorySize, AT_SMEM);

    const dim3 blk(256);

    // --- fp16 conversion of GEMM operands ---
    {
        const size_t nx = (size_t)M * E_DIM / 4;
        to_half_kernel<<<(unsigned)((nx + 255) / 256), blk>>>(x, xh, nx);
        const size_t nw = (size_t)E_DIM * E_DIM / 4;
        to_half_kernel<<<(unsigned)((nw + 255) / 256), blk>>>(Wq, Wqh, nw);
        to_half_kernel<<<(unsigned)((nw + 255) / 256), blk>>>(Wk, Wkh, nw);
        to_half_kernel<<<(unsigned)((nw + 255) / 256), blk>>>(Wv, Wvh, nw);
        const size_t nf = (size_t)E_DIM * HID_DIM / 4;
        to_half_kernel<<<(unsigned)((nf + 255) / 256), blk>>>(W1, W1h, nf);
        to_half_kernel<<<(unsigned)((nf + 255) / 256), blk>>>(W2, W2h, nf);
    }

    // Merged QKV projection -> fp16 Q/K/V (only consumed by attention)
    GemmOuts qkv;
    qkv.B[0] = Wqh; qkv.B[1] = Wkh; qkv.B[2] = Wvh;
    qkv.bias[0] = bq; qkv.bias[1] = bk; qkv.bias[2] = bv;
    qkv.C[0] = Qh; qkv.C[1] = Kh; qkv.C[2] = Vh;
    gemm_fp16<0,1><<<dim3(E_DIM / 128, M / 128, 3), blk, GEMM_SMEM_BYTES>>>(xh, qkv, M, E_DIM, E_DIM);

    window_attn_mma<<<M / WSZ, blk, AT_SMEM>>>(Qh, Kh, Vh, Ap);
    add_ln<1><<<M, blk>>>(x, Ap, g1, be1, X1p, X1h);

    // FFN1: A = fp16 X1, output H in fp16 (consumed by FFN2)
    GemmOuts f1; f1.B[0] = W1h; f1.bias[0] = b1; f1.C[0] = Hh;
    f1.B[1] = f1.B[2] = W1h; f1.bias[1] = f1.bias[2] = b1; f1.C[1] = f1.C[2] = Hh;
    gemm_fp16<1,1><<<dim3(HID_DIM / 128, M / 128, 1), blk, GEMM_SMEM_BYTES>>>(X1h, f1, M, HID_DIM, E_DIM);

    GemmOuts f2; f2.B[0] = W2h; f2.bias[0] = b2; f2.C[0] = Fp;
    f2.B[1] = f2.B[2] = W2h; f2.bias[1] = f2.bias[2] = b2; f2.C[1] = f2.C[2] = Fp;
    gemm_fp16<0,0><<<dim3(E_DIM / 128, M / 128, 1), blk, GEMM_SMEM_BYTES>>>(Hh, f2, M, E_DIM, HID_DIM);

    add_ln<0><<<M, blk>>>(X1p, Fp, g2, be2, out, nullptr);
}